// round 10
// baseline (speedup 1.0000x reference)
#include <cuda_runtime.h>

#define TT 64
#define BB 1024
#define II 64
#define HH 256

__device__ float g_hs[(size_t)TT * BB * HH];
__device__ float g_WT[HH * HH];   // WT[k][h] = W_hh[h][k]

typedef unsigned long long u64;

#define FMA_F32X2(d, a, b, c) \
    asm("fma.rn.f32x2 %0, %1, %2, %3;" : "=l"(d) : "l"(a), "l"(b), "l"(c))
#define PACK_F32X2(out, lo, hi) \
    asm("mov.b64 %0, {%1, %2};" : "=l"(out) : "f"(lo), "f"(hi))
#define UNPACK_F32X2(lo, hi, in) \
    asm("mov.b64 {%0, %1}, %2;" : "=f"(lo), "=f"(hi) : "l"(in))

// ---------------------------------------------------------------------------
// Kernel 0: transpose W_hh (one-time, 256 KB)
// ---------------------------------------------------------------------------
__global__ void __launch_bounds__(256) wt_kernel(const float* __restrict__ W_hh)
{
    const int k = blockIdx.x;
    const int h = threadIdx.x;
    g_WT[k * HH + h] = W_hh[h * HH + k];
}

// ---------------------------------------------------------------------------
// Kernel 1: g_hs[t,b,h] = data[t,b,:] . W_ih[h,:] + b_ih[h] + b_hh[h]
// ---------------------------------------------------------------------------
__global__ void __launch_bounds__(256) xw_kernel(
    const float* __restrict__ data,
    const float* __restrict__ W_ih,
    const float* __restrict__ b_ih,
    const float* __restrict__ b_hh)
{
    __shared__ float sX[256];
    const int tid = threadIdx.x;
    const long r0 = (long)blockIdx.x * 64;

    float w[64];
    const float4* W4 = reinterpret_cast<const float4*>(W_ih) + tid * 16;
#pragma unroll
    for (int c = 0; c < 16; c++) {
        float4 v = W4[c];
        w[4*c+0] = v.x; w[4*c+1] = v.y; w[4*c+2] = v.z; w[4*c+3] = v.w;
    }
    const float bsum = b_ih[tid] + b_hh[tid];

    for (int rg = 0; rg < 16; rg++) {
        __syncthreads();
        sX[tid] = data[r0 * II + rg * 256 + tid];
        __syncthreads();
        float a0 = bsum, a1 = bsum, a2 = bsum, a3 = bsum;
        const float4* X4 = reinterpret_cast<const float4*>(sX);
#pragma unroll
        for (int c = 0; c < 16; c++) {
            float4 x;
            x = X4[c];      a0 += x.x*w[4*c] + x.y*w[4*c+1] + x.z*w[4*c+2] + x.w*w[4*c+3];
            x = X4[16+c];   a1 += x.x*w[4*c] + x.y*w[4*c+1] + x.z*w[4*c+2] + x.w*w[4*c+3];
            x = X4[32+c];   a2 += x.x*w[4*c] + x.y*w[4*c+1] + x.z*w[4*c+2] + x.w*w[4*c+3];
            x = X4[48+c];   a3 += x.x*w[4*c] + x.y*w[4*c+1] + x.z*w[4*c+2] + x.w*w[4*c+3];
        }
        long r = r0 + rg * 4;
        g_hs[(r+0)*HH + tid] = a0;
        g_hs[(r+1)*HH + tid] = a1;
        g_hs[(r+2)*HH + tid] = a2;
        g_hs[(r+3)*HH + tid] = a3;
    }
}

// ---------------------------------------------------------------------------
// Kernel 2: persistent RNN scan, k-split (round-9 version — each W line is
// read exactly once per block per step; no L1 thrash).
// 128 blocks x 512 threads. Thread (kq = tid>>6, hw = tid&63): k-range
// [32kq, 32kq+32), 4 contiguous h. Partials summed via smem; 2 barriers/step.
// ---------------------------------------------------------------------------
__global__ void __launch_bounds__(512) rnn_scan_kernel(
    const float* __restrict__ h0_in)
{
    extern __shared__ float sm[];
    float* hp   = sm;                 // [2][8][260]
    float* part = sm + 2 * 8 * 260;   // [8][2048]

    const int tid = threadIdx.x;
    const int kq = tid >> 6;          // 0..7
    const int hw = tid & 63;          // float4 column
    const int b0 = blockIdx.x * 8;

    for (int m = tid; m < 2048; m += 512) {
        int bb = m >> 8, k = m & 255;
        hp[bb * 260 + k] = h0_in[(size_t)(b0 + bb) * HH + k];
    }
    __syncthreads();

    const int off = tid * 4;
    const int rb_b = off >> 8;
    const int rb_h = off & 255;

    for (int t = 0; t < TT; t++) {
        const int rb = t & 1;
        const float* hpc = hp + rb * 8 * 260;

        u64 acc[8][2];
#pragma unroll
        for (int bb = 0; bb < 8; bb++) { acc[bb][0] = 0ULL; acc[bb][1] = 0ULL; }

#pragma unroll 2
        for (int k4 = 0; k4 < 8; k4++) {
            const int k = kq * 32 + k4 * 4;
            const ulonglong2* wr =
                reinterpret_cast<const ulonglong2*>(g_WT + (size_t)k * HH) + hw;
            ulonglong2 w0 = wr[0];
            ulonglong2 w1 = wr[64];
            ulonglong2 w2 = wr[128];
            ulonglong2 w3 = wr[192];
#pragma unroll
            for (int bb = 0; bb < 8; bb++) {
                float4 hv = *reinterpret_cast<const float4*>(hpc + bb * 260 + k);
                u64 hd;
                PACK_F32X2(hd, hv.x, hv.x);
                FMA_F32X2(acc[bb][0], w0.x, hd, acc[bb][0]);
                FMA_F32X2(acc[bb][1], w0.y, hd, acc[bb][1]);
                PACK_F32X2(hd, hv.y, hv.y);
                FMA_F32X2(acc[bb][0], w1.x, hd, acc[bb][0]);
                FMA_F32X2(acc[bb][1], w1.y, hd, acc[bb][1]);
                PACK_F32X2(hd, hv.z, hv.z);
                FMA_F32X2(acc[bb][0], w2.x, hd, acc[bb][0]);
                FMA_F32X2(acc[bb][1], w2.y, hd, acc[bb][1]);
                PACK_F32X2(hd, hv.w, hv.w);
                FMA_F32X2(acc[bb][0], w3.x, hd, acc[bb][0]);
                FMA_F32X2(acc[bb][1], w3.y, hd, acc[bb][1]);
            }
        }

#pragma unroll
        for (int bb = 0; bb < 8; bb++) {
            float f0, f1, f2, f3;
            UNPACK_F32X2(f0, f1, acc[bb][0]);
            UNPACK_F32X2(f2, f3, acc[bb][1]);
            *reinterpret_cast<float4*>(part + kq * 2048 + bb * 256 + hw * 4) =
                make_float4(f0, f1, f2, f3);
        }
        __syncthreads();

        {
            float* hs_t = g_hs + (size_t)t * BB * HH;
            float4 r = *reinterpret_cast<const float4*>(
                hs_t + (size_t)(b0 + rb_b) * HH + rb_h);
#pragma unroll
            for (int q = 0; q < 8; q++) {
                float4 pv = *reinterpret_cast<const float4*>(part + q * 2048 + off);
                r.x += pv.x; r.y += pv.y; r.z += pv.z; r.w += pv.w;
            }
            r.x = fmaxf(r.x, 0.f); r.y = fmaxf(r.y, 0.f);
            r.z = fmaxf(r.z, 0.f); r.w = fmaxf(r.w, 0.f);
            *reinterpret_cast<float4*>(
                hs_t + (size_t)(b0 + rb_b) * HH + rb_h) = r;
            *reinterpret_cast<float4*>(
                hp + (rb ^ 1) * 8 * 260 + rb_b * 260 + rb_h) = r;
        }
        __syncthreads();
    }
}

// ---------------------------------------------------------------------------
// Kernel 3: attention — round-7 version VERBATIM (validated: 128 regs,
// 2 blocks/SM, no spills). Grid = 2048 (2 blocks per b, 32 i-rows each).
// ---------------------------------------------------------------------------
#define GSH_STRIDE 264     // 256 h + 8 pad (words)

__global__ void __launch_bounds__(256, 2) attn_kernel(
    const int* __restrict__ nine_idx,
    const float* __restrict__ W_lin,
    const float* __restrict__ b_lin,
    float* __restrict__ out)
{
    __shared__ float Gsh[2][9 * GSH_STRIDE];
    __shared__ float sWl[512];
    __shared__ int   sidx[9];

    const int tid   = threadIdx.x;
    const int b     = blockIdx.x >> 1;
    const int ibase = (blockIdx.x & 1) * 32;
    const int iq    = tid >> 4;
    const int hq    = tid & 15;
    const int iA    = ibase + 2 * iq;
    const int iB    = iA + 1;
    const int hc    = 16 * hq;

    if (tid < 9) sidx[tid] = nine_idx[b * 9 + tid];
    sWl[tid] = W_lin[tid];
    sWl[256 + tid] = W_lin[256 + tid];
    __syncthreads();

    int idxr[9];
#pragma unroll
    for (int n = 0; n < 9; n++) idxr[n] = sidx[n];

    u64 hspA[8], hspB[8];
    {
        const ulonglong2* HA = reinterpret_cast<const ulonglong2*>(
            g_hs + ((size_t)iA * BB + b) * HH + hc);
        const ulonglong2* HB = reinterpret_cast<const ulonglong2*>(
            g_hs + ((size_t)iB * BB + b) * HH + hc);
#pragma unroll
        for (int q = 0; q < 4; q++) {
            ulonglong2 va = HA[q];
            ulonglong2 vb = HB[q];
            hspA[2*q] = va.x; hspA[2*q+1] = va.y;
            hspB[2*q] = vb.x; hspB[2*q+1] = vb.y;
        }
    }

    u64 acc2A[8], acc2B[8];
#pragma unroll
    for (int e = 0; e < 8; e++) { acc2A[e] = 0ULL; acc2B[e] = 0ULL; }

    const float bl = b_lin[0];

    float gr[9];
#pragma unroll
    for (int n = 0; n < 9; n++) {
        int iv = idxr[n];
        gr[n] = (iv < BB) ? g_hs[(size_t)iv * HH + tid] : 0.f;
    }

    float* out_attn = out + (size_t)TT * BB;

    for (int j = 0; j < TT; j++) {
        float* gh = Gsh[j & 1];
#pragma unroll
        for (int n = 0; n < 9; n++) gh[n * GSH_STRIDE + tid] = gr[n];
        __syncthreads();

        if (j < TT - 1) {
            const float* src = g_hs + (size_t)(j + 1) * BB * HH;
#pragma unroll
            for (int n = 0; n < 9; n++) {
                int iv = idxr[n];
                gr[n] = (iv < BB) ? src[(size_t)iv * HH + tid] : 0.f;
            }
        }

        float pA[9], pB[9];
#pragma unroll
        for (int n = 0; n < 9; n++) {
            const ulonglong2* gp = reinterpret_cast<const ulonglong2*>(
                gh + n * GSH_STRIDE + hc);
            u64 sA = 0ULL, sB = 0ULL;
#pragma unroll
            for (int q = 0; q < 4; q++) {
                ulonglong2 gq = gp[q];
                FMA_F32X2(sA, gq.x, hspA[2*q],   sA);
                FMA_F32X2(sB, gq.x, hspB[2*q],   sB);
                FMA_F32X2(sA, gq.y, hspA[2*q+1], sA);
                FMA_F32X2(sB, gq.y, hspB[2*q+1], sB);
            }
            float l0, l1;
            UNPACK_F32X2(l0, l1, sA); pA[n] = l0 + l1;
            UNPACK_F32X2(l0, l1, sB); pB[n] = l0 + l1;
        }

#pragma unroll
        for (int n = 0; n < 9; n++) {
            float vA = pA[n], vB = pB[n];
            vA += __shfl_xor_sync(0xffffffffu, vA, 1);
            vA += __shfl_xor_sync(0xffffffffu, vA, 2);
            vA += __shfl_xor_sync(0xffffffffu, vA, 4);
            vA += __shfl_xor_sync(0xffffffffu, vA, 8);
            vB += __shfl_xor_sync(0xffffffffu, vB, 1);
            vB += __shfl_xor_sync(0xffffffffu, vB, 2);
            vB += __shfl_xor_sync(0xffffffffu, vB, 4);
            vB += __shfl_xor_sync(0xffffffffu, vB, 8);
            pA[n] = vA; pB[n] = vB;
        }

        {
            float mA = pA[0], mB = pB[0];
#pragma unroll
            for (int n = 1; n < 9; n++) { mA = fmaxf(mA, pA[n]); mB = fmaxf(mB, pB[n]); }
            float sumA = 0.f, sumB = 0.f;
#pragma unroll
            for (int n = 0; n < 9; n++) {
                pA[n] = __expf(pA[n] - mA); sumA += pA[n];
                pB[n] = __expf(pB[n] - mB); sumB += pB[n];
            }
            float rA = 1.f / sumA, rB = 1.f / sumB;
#pragma unroll
            for (int n = 0; n < 9; n++) { pA[n] *= rA; pB[n] *= rB; }
        }

        if (hq < 9) {
            out_attn[(((size_t)(iA * TT + j)) * BB + b) * 9 + hq] = pA[hq];
            out_attn[(((size_t)(iB * TT + j)) * BB + b) * 9 + hq] = pB[hq];
        }

        if (j < iB) {
            const bool dA = (j < iA);
#pragma unroll
            for (int n = 0; n < 9; n++) {
                float vA = dA ? pA[n] : 0.f;
                u64 pdA, pdB;
                PACK_F32X2(pdA, vA, vA);
                PACK_F32X2(pdB, pB[n], pB[n]);
                const ulonglong2* gp = reinterpret_cast<const ulonglong2*>(
                    gh + n * GSH_STRIDE + hc);
#pragma unroll
                for (int q = 0; q < 4; q++) {
                    ulonglong2 gq = gp[q];
                    FMA_F32X2(acc2A[2*q],   pdA, gq.x, acc2A[2*q]);
                    FMA_F32X2(acc2A[2*q+1], pdA, gq.y, acc2A[2*q+1]);
                    FMA_F32X2(acc2B[2*q],   pdB, gq.x, acc2B[2*q]);
                    FMA_F32X2(acc2B[2*q+1], pdB, gq.y, acc2B[2*q+1]);
                }
            }
        }
    }

#pragma unroll
    for (int i = 0; i < 2; i++) {
        const int gi = (i == 0) ? iA : iB;
        const u64* hsp = (i == 0) ? hspA : hspB;
        const u64* ac  = (i == 0) ? acc2A : acc2B;
        float t = 0.f;
#pragma unroll
        for (int e = 0; e < 8; e++) {
            const int h0 = hc + 2 * e;
            float h0v, h1v, a0v, a1v;
            UNPACK_F32X2(h0v, h1v, hsp[e]);
            UNPACK_F32X2(a0v, a1v, ac[e]);
            if (gi == 0) { a0v = h0v; a1v = h1v; }
            t += a0v * sWl[h0]     + h0v * sWl[256 + h0];
            t += a1v * sWl[h0 + 1] + h1v * sWl[256 + h0 + 1];
        }
        t += __shfl_xor_sync(0xffffffffu, t, 1);
        t += __shfl_xor_sync(0xffffffffu, t, 2);
        t += __shfl_xor_sync(0xffffffffu, t, 4);
        t += __shfl_xor_sync(0xffffffffu, t, 8);
        if (hq == 0)
            out[(size_t)gi * BB + b] = fmaxf(t + bl, 0.f);
    }
}

// ---------------------------------------------------------------------------
extern "C" void kernel_launch(void* const* d_in, const int* in_sizes, int n_in,
                              void* d_out, int out_size)
{
    const float* data  = (const float*)d_in[0];
    const int*   nidx  = (const int*)d_in[1];
    /* d_in[2] = haven_flag (always 0, branch unused) */
    const float* h0    = (const float*)d_in[3];
    const float* W_ih  = (const float*)d_in[4];
    const float* W_hh  = (const float*)d_in[5];
    const float* b_ih  = (const float*)d_in[6];
    const float* b_hh  = (const float*)d_in[7];
    const float* W_lin = (const float*)d_in[8];
    const float* b_lin = (const float*)d_in[9];
    float* out = (float*)d_out;

    (void)in_sizes; (void)n_in; (void)out_size;

    wt_kernel<<<256, 256>>>(W_hh);
    xw_kernel<<<1024, 256>>>(data, W_ih, b_ih, b_hh);

    const int rnn_smem = (2 * 8 * 260 + 8 * 2048) * (int)sizeof(float);
    cudaFuncSetAttribute(rnn_scan_kernel,
                         cudaFuncAttributeMaxDynamicSharedMemorySize, rnn_smem);
    rnn_scan_kernel<<<128, 512, rnn_smem>>>(h0);

    attn_kernel<<<2048, 256>>>(nidx, W_lin, b_lin, out);
}

// round 11
// speedup vs baseline: 3.3676x; 3.3676x over previous
#include <cuda_runtime.h>

#define TT 64
#define BB 1024
#define II 64
#define HH 256

__device__ float g_hs[(size_t)TT * BB * HH];
__device__ float g_WT[HH * HH];   // WT[k][h] = W_hh[h][k]

typedef unsigned long long u64;

#define FMA_F32X2(d, a, b, c) \
    asm("fma.rn.f32x2 %0, %1, %2, %3;" : "=l"(d) : "l"(a), "l"(b), "l"(c))
#define PACK_F32X2(out, lo, hi) \
    asm("mov.b64 %0, {%1, %2};" : "=l"(out) : "f"(lo), "f"(hi))
#define UNPACK_F32X2(lo, hi, in) \
    asm("mov.b64 {%0, %1}, %2;" : "=f"(lo), "=f"(hi) : "l"(in))

// ---------------------------------------------------------------------------
// Kernel 0: transpose W_hh (one-time, 256 KB)
// ---------------------------------------------------------------------------
__global__ void __launch_bounds__(256) wt_kernel(const float* __restrict__ W_hh)
{
    const int k = blockIdx.x;
    const int h = threadIdx.x;
    g_WT[k * HH + h] = W_hh[h * HH + k];
}

// ---------------------------------------------------------------------------
// Kernel 1: g_hs[t,b,h] = data[t,b,:] . W_ih[h,:] + b_ih[h] + b_hh[h]
// ---------------------------------------------------------------------------
__global__ void __launch_bounds__(256) xw_kernel(
    const float* __restrict__ data,
    const float* __restrict__ W_ih,
    const float* __restrict__ b_ih,
    const float* __restrict__ b_hh)
{
    __shared__ float sX[256];
    const int tid = threadIdx.x;
    const long r0 = (long)blockIdx.x * 64;

    float w[64];
    const float4* W4 = reinterpret_cast<const float4*>(W_ih) + tid * 16;
#pragma unroll
    for (int c = 0; c < 16; c++) {
        float4 v = W4[c];
        w[4*c+0] = v.x; w[4*c+1] = v.y; w[4*c+2] = v.z; w[4*c+3] = v.w;
    }
    const float bsum = b_ih[tid] + b_hh[tid];

    for (int rg = 0; rg < 16; rg++) {
        __syncthreads();
        sX[tid] = data[r0 * II + rg * 256 + tid];
        __syncthreads();
        float a0 = bsum, a1 = bsum, a2 = bsum, a3 = bsum;
        const float4* X4 = reinterpret_cast<const float4*>(sX);
#pragma unroll
        for (int c = 0; c < 16; c++) {
            float4 x;
            x = X4[c];      a0 += x.x*w[4*c] + x.y*w[4*c+1] + x.z*w[4*c+2] + x.w*w[4*c+3];
            x = X4[16+c];   a1 += x.x*w[4*c] + x.y*w[4*c+1] + x.z*w[4*c+2] + x.w*w[4*c+3];
            x = X4[32+c];   a2 += x.x*w[4*c] + x.y*w[4*c+1] + x.z*w[4*c+2] + x.w*w[4*c+3];
            x = X4[48+c];   a3 += x.x*w[4*c] + x.y*w[4*c+1] + x.z*w[4*c+2] + x.w*w[4*c+3];
        }
        long r = r0 + rg * 4;
        g_hs[(r+0)*HH + tid] = a0;
        g_hs[(r+1)*HH + tid] = a1;
        g_hs[(r+2)*HH + tid] = a2;
        g_hs[(r+3)*HH + tid] = a3;
    }
}

// ---------------------------------------------------------------------------
// Kernel 2: persistent RNN scan, k-split (validated in R10: −585 us vs old).
// 128 blocks x 512 threads. Thread (kq = tid>>6, hw = tid&63): k-range
// [32kq, 32kq+32), 4 contiguous h. W read once per block-step (coalesced,
// L2-resident). Partials summed via smem; 2 barriers/step.
// ---------------------------------------------------------------------------
__global__ void __launch_bounds__(512) rnn_scan_kernel(
    const float* __restrict__ h0_in)
{
    extern __shared__ float sm[];
    float* hp   = sm;                 // [2][8][260]
    float* part = sm + 2 * 8 * 260;   // [8][2048]

    const int tid = threadIdx.x;
    const int kq = tid >> 6;
    const int hw = tid & 63;
    const int b0 = blockIdx.x * 8;

    for (int m = tid; m < 2048; m += 512) {
        int bb = m >> 8, k = m & 255;
        hp[bb * 260 + k] = h0_in[(size_t)(b0 + bb) * HH + k];
    }
    __syncthreads();

    const int off = tid * 4;
    const int rb_b = off >> 8;
    const int rb_h = off & 255;

    for (int t = 0; t < TT; t++) {
        const int rb = t & 1;
        const float* hpc = hp + rb * 8 * 260;

        u64 acc[8][2];
#pragma unroll
        for (int bb = 0; bb < 8; bb++) { acc[bb][0] = 0ULL; acc[bb][1] = 0ULL; }

#pragma unroll 2
        for (int k4 = 0; k4 < 8; k4++) {
            const int k = kq * 32 + k4 * 4;
            const ulonglong2* wr =
                reinterpret_cast<const ulonglong2*>(g_WT + (size_t)k * HH) + hw;
            ulonglong2 w0 = wr[0];
            ulonglong2 w1 = wr[64];
            ulonglong2 w2 = wr[128];
            ulonglong2 w3 = wr[192];
#pragma unroll
            for (int bb = 0; bb < 8; bb++) {
                float4 hv = *reinterpret_cast<const float4*>(hpc + bb * 260 + k);
                u64 hd;
                PACK_F32X2(hd, hv.x, hv.x);
                FMA_F32X2(acc[bb][0], w0.x, hd, acc[bb][0]);
                FMA_F32X2(acc[bb][1], w0.y, hd, acc[bb][1]);
                PACK_F32X2(hd, hv.y, hv.y);
                FMA_F32X2(acc[bb][0], w1.x, hd, acc[bb][0]);
                FMA_F32X2(acc[bb][1], w1.y, hd, acc[bb][1]);
                PACK_F32X2(hd, hv.z, hv.z);
                FMA_F32X2(acc[bb][0], w2.x, hd, acc[bb][0]);
                FMA_F32X2(acc[bb][1], w2.y, hd, acc[bb][1]);
                PACK_F32X2(hd, hv.w, hv.w);
                FMA_F32X2(acc[bb][0], w3.x, hd, acc[bb][0]);
                FMA_F32X2(acc[bb][1], w3.y, hd, acc[bb][1]);
            }
        }

#pragma unroll
        for (int bb = 0; bb < 8; bb++) {
            float f0, f1, f2, f3;
            UNPACK_F32X2(f0, f1, acc[bb][0]);
            UNPACK_F32X2(f2, f3, acc[bb][1]);
            *reinterpret_cast<float4*>(part + kq * 2048 + bb * 256 + hw * 4) =
                make_float4(f0, f1, f2, f3);
        }
        __syncthreads();

        {
            float* hs_t = g_hs + (size_t)t * BB * HH;
            float4 r = *reinterpret_cast<const float4*>(
                hs_t + (size_t)(b0 + rb_b) * HH + rb_h);
#pragma unroll
            for (int q = 0; q < 8; q++) {
                float4 pv = *reinterpret_cast<const float4*>(part + q * 2048 + off);
                r.x += pv.x; r.y += pv.y; r.z += pv.z; r.w += pv.w;
            }
            r.x = fmaxf(r.x, 0.f); r.y = fmaxf(r.y, 0.f);
            r.z = fmaxf(r.z, 0.f); r.w = fmaxf(r.w, 0.f);
            *reinterpret_cast<float4*>(
                hs_t + (size_t)(b0 + rb_b) * HH + rb_h) = r;
            *reinterpret_cast<float4*>(
                hp + (rb ^ 1) * 8 * 260 + rb_b * 260 + rb_h) = r;
        }
        __syncthreads();
    }
}

// ---------------------------------------------------------------------------
// Kernel 3: attention — the TRUE round-7 kernel (dual Gsn/Gsh layout,
// measured: 128 regs NO spill, L1 78%, fma 39%, 2365us total).
// Grid = 2048 (2 blocks per b, 32 i-rows each), 256 threads.
// ---------------------------------------------------------------------------
#define GSN_STRIDE 10      // 9 n + 1 pad (words)  -> conflict-free LDS.64
#define GSH_STRIDE 264     // 256 h + 8 pad (words)

__global__ void __launch_bounds__(256, 2) attn_kernel(
    const int* __restrict__ nine_idx,
    const float* __restrict__ W_lin,
    const float* __restrict__ b_lin,
    float* __restrict__ out)
{
    __shared__ float Gsn[2][256 * GSN_STRIDE];
    __shared__ float Gsh[2][9 * GSH_STRIDE];
    __shared__ float sWl[512];
    __shared__ int   sidx[9];

    const int tid   = threadIdx.x;
    const int b     = blockIdx.x >> 1;
    const int ibase = (blockIdx.x & 1) * 32;
    const int iq    = tid >> 4;
    const int hq    = tid & 15;
    const int iA    = ibase + 2 * iq;
    const int iB    = iA + 1;

    if (tid < 9) sidx[tid] = nine_idx[b * 9 + tid];
    sWl[tid] = W_lin[tid];
    sWl[256 + tid] = W_lin[256 + tid];
    __syncthreads();

    int idxr[9];
#pragma unroll
    for (int n = 0; n < 9; n++) idxr[n] = sidx[n];

    float hsA[16], hsB[16];
    {
        const float* HA = g_hs + ((size_t)iA * BB + b) * HH + hq;
        const float* HB = g_hs + ((size_t)iB * BB + b) * HH + hq;
#pragma unroll
        for (int e = 0; e < 16; e++) { hsA[e] = HA[16 * e]; hsB[e] = HB[16 * e]; }
    }

    u64 acc2[2][4][2];
#pragma unroll
    for (int i = 0; i < 2; i++)
#pragma unroll
        for (int c = 0; c < 4; c++) { acc2[i][c][0] = 0ULL; acc2[i][c][1] = 0ULL; }

    const float bl = b_lin[0];

    float gr[9];
#pragma unroll
    for (int n = 0; n < 9; n++) {
        int iv = idxr[n];
        gr[n] = (iv < BB) ? g_hs[(size_t)iv * HH + tid] : 0.f;
    }

    float* out_attn = out + (size_t)TT * BB;

    for (int j = 0; j < TT; j++) {
        float* gn = Gsn[j & 1];
        float* gh = Gsh[j & 1];
#pragma unroll
        for (int n = 0; n < 9; n++) gn[tid * GSN_STRIDE + n] = gr[n];
#pragma unroll
        for (int n = 0; n < 9; n++) gh[n * GSH_STRIDE + tid] = gr[n];
        __syncthreads();

        if (j < TT - 1) {
            const float* src = g_hs + (size_t)(j + 1) * BB * HH;
#pragma unroll
            for (int n = 0; n < 9; n++) {
                int iv = idxr[n];
                gr[n] = (iv < BB) ? src[(size_t)iv * HH + tid] : 0.f;
            }
        }

        u64 s2A[4], s2B[4];
        float s8A = 0.f, s8B = 0.f;
#pragma unroll
        for (int p = 0; p < 4; p++) { s2A[p] = 0ULL; s2B[p] = 0ULL; }

#pragma unroll
        for (int e = 0; e < 16; e++) {
            const float* base = gn + (hq + 16 * e) * GSN_STRIDE;
            u64 g01 = *reinterpret_cast<const u64*>(base);
            u64 g23 = *reinterpret_cast<const u64*>(base + 2);
            u64 g45 = *reinterpret_cast<const u64*>(base + 4);
            u64 g67 = *reinterpret_cast<const u64*>(base + 6);
            float g8v = base[8];
            float xA = hsA[e], xB = hsB[e];
            u64 xdA, xdB;
            PACK_F32X2(xdA, xA, xA);
            PACK_F32X2(xdB, xB, xB);
            FMA_F32X2(s2A[0], g01, xdA, s2A[0]);
            FMA_F32X2(s2A[1], g23, xdA, s2A[1]);
            FMA_F32X2(s2A[2], g45, xdA, s2A[2]);
            FMA_F32X2(s2A[3], g67, xdA, s2A[3]);
            FMA_F32X2(s2B[0], g01, xdB, s2B[0]);
            FMA_F32X2(s2B[1], g23, xdB, s2B[1]);
            FMA_F32X2(s2B[2], g45, xdB, s2B[2]);
            FMA_F32X2(s2B[3], g67, xdB, s2B[3]);
            s8A += xA * g8v;
            s8B += xB * g8v;
        }

        float pA[9], pB[9];
#pragma unroll
        for (int p = 0; p < 4; p++) {
            UNPACK_F32X2(pA[2*p], pA[2*p+1], s2A[p]);
            UNPACK_F32X2(pB[2*p], pB[2*p+1], s2B[p]);
        }
        pA[8] = s8A; pB[8] = s8B;

#pragma unroll
        for (int n = 0; n < 9; n++) {
            float vA = pA[n], vB = pB[n];
            vA += __shfl_xor_sync(0xffffffffu, vA, 1);
            vA += __shfl_xor_sync(0xffffffffu, vA, 2);
            vA += __shfl_xor_sync(0xffffffffu, vA, 4);
            vA += __shfl_xor_sync(0xffffffffu, vA, 8);
            vB += __shfl_xor_sync(0xffffffffu, vB, 1);
            vB += __shfl_xor_sync(0xffffffffu, vB, 2);
            vB += __shfl_xor_sync(0xffffffffu, vB, 4);
            vB += __shfl_xor_sync(0xffffffffu, vB, 8);
            pA[n] = vA; pB[n] = vB;
        }

        {
            float mA = pA[0], mB = pB[0];
#pragma unroll
            for (int n = 1; n < 9; n++) { mA = fmaxf(mA, pA[n]); mB = fmaxf(mB, pB[n]); }
            float sumA = 0.f, sumB = 0.f;
#pragma unroll
            for (int n = 0; n < 9; n++) {
                pA[n] = __expf(pA[n] - mA); sumA += pA[n];
                pB[n] = __expf(pB[n] - mB); sumB += pB[n];
            }
            float rA = 1.f / sumA, rB = 1.f / sumB;
#pragma unroll
            for (int n = 0; n < 9; n++) { pA[n] *= rA; pB[n] *= rB; }
        }

        if (hq < 9) {
            out_attn[(((size_t)(iA * TT + j)) * BB + b) * 9 + hq] = pA[hq];
            out_attn[(((size_t)(iB * TT + j)) * BB + b) * 9 + hq] = pB[hq];
        }

        if (j < iB) {
            const bool dA = (j < iA);
#pragma unroll
            for (int n = 0; n < 9; n++) {
                float vA = dA ? pA[n] : 0.f;
                u64 pdA, pdB;
                PACK_F32X2(pdA, vA, vA);
                PACK_F32X2(pdB, pB[n], pB[n]);
                const float* rowp = gh + n * GSH_STRIDE + 4 * hq;
#pragma unroll
                for (int c = 0; c < 4; c++) {
                    ulonglong2 gv = *reinterpret_cast<const ulonglong2*>(rowp + 64 * c);
                    FMA_F32X2(acc2[0][c][0], pdA, gv.x, acc2[0][c][0]);
                    FMA_F32X2(acc2[0][c][1], pdA, gv.y, acc2[0][c][1]);
                    FMA_F32X2(acc2[1][c][0], pdB, gv.x, acc2[1][c][0]);
                    FMA_F32X2(acc2[1][c][1], pdB, gv.y, acc2[1][c][1]);
                }
            }
        }
    }

#pragma unroll
    for (int i = 0; i < 2; i++) {
        const int gi = (i == 0) ? iA : iB;
        const float* hrow = g_hs + ((size_t)gi * BB + b) * HH;
        float t = 0.f;
#pragma unroll
        for (int c = 0; c < 4; c++) {
            const int h0 = 4 * hq + 64 * c;
            float4 hv = *reinterpret_cast<const float4*>(hrow + h0);
            float a0, a1, a2, a3;
            UNPACK_F32X2(a0, a1, acc2[i][c][0]);
            UNPACK_F32X2(a2, a3, acc2[i][c][1]);
            if (gi == 0) { a0 = hv.x; a1 = hv.y; a2 = hv.z; a3 = hv.w; }
            t += a0 * sWl[h0]   + hv.x * sWl[256 + h0];
            t += a1 * sWl[h0+1] + hv.y * sWl[256 + h0 + 1];
            t += a2 * sWl[h0+2] + hv.z * sWl[256 + h0 + 2];
            t += a3 * sWl[h0+3] + hv.w * sWl[256 + h0 + 3];
        }
        t += __shfl_xor_sync(0xffffffffu, t, 1);
        t += __shfl_xor_sync(0xffffffffu, t, 2);
        t += __shfl_xor_sync(0xffffffffu, t, 4);
        t += __shfl_xor_sync(0xffffffffu, t, 8);
        if (hq == 0)
            out[(size_t)gi * BB + b] = fmaxf(t + bl, 0.f);
    }
}

// ---------------------------------------------------------------------------
extern "C" void kernel_launch(void* const* d_in, const int* in_sizes, int n_in,
                              void* d_out, int out_size)
{
    const float* data  = (const float*)d_in[0];
    const int*   nidx  = (const int*)d_in[1];
    /* d_in[2] = haven_flag (always 0, branch unused) */
    const float* h0    = (const float*)d_in[3];
    const float* W_ih  = (const float*)d_in[4];
    const float* W_hh  = (const float*)d_in[5];
    const float* b_ih  = (const float*)d_in[6];
    const float* b_hh  = (const float*)d_in[7];
    const float* W_lin = (const float*)d_in[8];
    const float* b_lin = (const float*)d_in[9];
    float* out = (float*)d_out;

    (void)in_sizes; (void)n_in; (void)out_size;

    wt_kernel<<<256, 256>>>(W_hh);
    xw_kernel<<<1024, 256>>>(data, W_ih, b_ih, b_hh);

    const int rnn_smem = (2 * 8 * 260 + 8 * 2048) * (int)sizeof(float);
    cudaFuncSetAttribute(rnn_scan_kernel,
                         cudaFuncAttributeMaxDynamicSharedMemorySize, rnn_smem);
    rnn_scan_kernel<<<128, 512, rnn_smem>>>(h0);

    attn_kernel<<<2048, 256>>>(nidx, W_lin, b_lin, out);
}

// round 13
// speedup vs baseline: 3.6244x; 1.0763x over previous
#include <cuda_runtime.h>

#define TT 64
#define BB 1024
#define II 64
#define HH 256

__device__ float g_hs[(size_t)TT * BB * HH];
__device__ float g_WT[HH * HH];   // WT[k][h] = W_hh[h][k]

typedef unsigned long long u64;

#define FMA_F32X2(d, a, b, c) \
    asm("fma.rn.f32x2 %0, %1, %2, %3;" : "=l"(d) : "l"(a), "l"(b), "l"(c))
#define PACK_F32X2(out, lo, hi) \
    asm("mov.b64 %0, {%1, %2};" : "=l"(out) : "f"(lo), "f"(hi))
#define UNPACK_F32X2(lo, hi, in) \
    asm("mov.b64 {%0, %1}, %2;" : "=f"(lo), "=f"(hi) : "l"(in))

// ---------------------------------------------------------------------------
// Kernel 0: transpose W_hh (one-time, 256 KB)
// ---------------------------------------------------------------------------
__global__ void __launch_bounds__(256) wt_kernel(const float* __restrict__ W_hh)
{
    const int k = blockIdx.x;
    const int h = threadIdx.x;
    g_WT[k * HH + h] = W_hh[h * HH + k];
}

// ---------------------------------------------------------------------------
// Kernel 1: g_hs[t,b,h] = data[t,b,:] . W_ih[h,:] + b_ih[h] + b_hh[h]
// ---------------------------------------------------------------------------
__global__ void __launch_bounds__(256) xw_kernel(
    const float* __restrict__ data,
    const float* __restrict__ W_ih,
    const float* __restrict__ b_ih,
    const float* __restrict__ b_hh)
{
    __shared__ float sX[256];
    const int tid = threadIdx.x;
    const long r0 = (long)blockIdx.x * 64;

    float w[64];
    const float4* W4 = reinterpret_cast<const float4*>(W_ih) + tid * 16;
#pragma unroll
    for (int c = 0; c < 16; c++) {
        float4 v = W4[c];
        w[4*c+0] = v.x; w[4*c+1] = v.y; w[4*c+2] = v.z; w[4*c+3] = v.w;
    }
    const float bsum = b_ih[tid] + b_hh[tid];

    for (int rg = 0; rg < 16; rg++) {
        __syncthreads();
        sX[tid] = data[r0 * II + rg * 256 + tid];
        __syncthreads();
        float a0 = bsum, a1 = bsum, a2 = bsum, a3 = bsum;
        const float4* X4 = reinterpret_cast<const float4*>(sX);
#pragma unroll
        for (int c = 0; c < 16; c++) {
            float4 x;
            x = X4[c];      a0 += x.x*w[4*c] + x.y*w[4*c+1] + x.z*w[4*c+2] + x.w*w[4*c+3];
            x = X4[16+c];   a1 += x.x*w[4*c] + x.y*w[4*c+1] + x.z*w[4*c+2] + x.w*w[4*c+3];
            x = X4[32+c];   a2 += x.x*w[4*c] + x.y*w[4*c+1] + x.z*w[4*c+2] + x.w*w[4*c+3];
            x = X4[48+c];   a3 += x.x*w[4*c] + x.y*w[4*c+1] + x.z*w[4*c+2] + x.w*w[4*c+3];
        }
        long r = r0 + rg * 4;
        g_hs[(r+0)*HH + tid] = a0;
        g_hs[(r+1)*HH + tid] = a1;
        g_hs[(r+2)*HH + tid] = a2;
        g_hs[(r+3)*HH + tid] = a3;
    }
}

// ---------------------------------------------------------------------------
// Kernel 2: persistent RNN scan, k-split (validated: each W line read once
// per block-step). 128 blocks x 512 threads; 2 barriers/step.
// ---------------------------------------------------------------------------
__global__ void __launch_bounds__(512) rnn_scan_kernel(
    const float* __restrict__ h0_in)
{
    extern __shared__ float sm[];
    float* hp   = sm;                 // [2][8][260]
    float* part = sm + 2 * 8 * 260;   // [8][2048]

    const int tid = threadIdx.x;
    const int kq = tid >> 6;
    const int hw = tid & 63;
    const int b0 = blockIdx.x * 8;

    for (int m = tid; m < 2048; m += 512) {
        int bb = m >> 8, k = m & 255;
        hp[bb * 260 + k] = h0_in[(size_t)(b0 + bb) * HH + k];
    }
    __syncthreads();

    const int off = tid * 4;
    const int rb_b = off >> 8;
    const int rb_h = off & 255;

    for (int t = 0; t < TT; t++) {
        const int rb = t & 1;
        const float* hpc = hp + rb * 8 * 260;

        u64 acc[8][2];
#pragma unroll
        for (int bb = 0; bb < 8; bb++) { acc[bb][0] = 0ULL; acc[bb][1] = 0ULL; }

#pragma unroll 2
        for (int k4 = 0; k4 < 8; k4++) {
            const int k = kq * 32 + k4 * 4;
            const ulonglong2* wr =
                reinterpret_cast<const ulonglong2*>(g_WT + (size_t)k * HH) + hw;
            ulonglong2 w0 = wr[0];
            ulonglong2 w1 = wr[64];
            ulonglong2 w2 = wr[128];
            ulonglong2 w3 = wr[192];
#pragma unroll
            for (int bb = 0; bb < 8; bb++) {
                float4 hv = *reinterpret_cast<const float4*>(hpc + bb * 260 + k);
                u64 hd;
                PACK_F32X2(hd, hv.x, hv.x);
                FMA_F32X2(acc[bb][0], w0.x, hd, acc[bb][0]);
                FMA_F32X2(acc[bb][1], w0.y, hd, acc[bb][1]);
                PACK_F32X2(hd, hv.y, hv.y);
                FMA_F32X2(acc[bb][0], w1.x, hd, acc[bb][0]);
                FMA_F32X2(acc[bb][1], w1.y, hd, acc[bb][1]);
                PACK_F32X2(hd, hv.z, hv.z);
                FMA_F32X2(acc[bb][0], w2.x, hd, acc[bb][0]);
                FMA_F32X2(acc[bb][1], w2.y, hd, acc[bb][1]);
                PACK_F32X2(hd, hv.w, hv.w);
                FMA_F32X2(acc[bb][0], w3.x, hd, acc[bb][0]);
                FMA_F32X2(acc[bb][1], w3.y, hd, acc[bb][1]);
            }
        }

#pragma unroll
        for (int bb = 0; bb < 8; bb++) {
            float f0, f1, f2, f3;
            UNPACK_F32X2(f0, f1, acc[bb][0]);
            UNPACK_F32X2(f2, f3, acc[bb][1]);
            *reinterpret_cast<float4*>(part + kq * 2048 + bb * 256 + hw * 4) =
                make_float4(f0, f1, f2, f3);
        }
        __syncthreads();

        {
            float* hs_t = g_hs + (size_t)t * BB * HH;
            float4 r = *reinterpret_cast<const float4*>(
                hs_t + (size_t)(b0 + rb_b) * HH + rb_h);
#pragma unroll
            for (int q = 0; q < 8; q++) {
                float4 pv = *reinterpret_cast<const float4*>(part + q * 2048 + off);
                r.x += pv.x; r.y += pv.y; r.z += pv.z; r.w += pv.w;
            }
            r.x = fmaxf(r.x, 0.f); r.y = fmaxf(r.y, 0.f);
            r.z = fmaxf(r.z, 0.f); r.w = fmaxf(r.w, 0.f);
            *reinterpret_cast<float4*>(
                hs_t + (size_t)(b0 + rb_b) * HH + rb_h) = r;
            *reinterpret_cast<float4*>(
                hp + (rb ^ 1) * 8 * 260 + rb_b * 260 + rb_h) = r;
        }
        __syncthreads();
    }
}

// ---------------------------------------------------------------------------
// Kernel 3: attention — round-11 base with the split-reduce butterfly:
// level-1 (xor 8) EXCHANGES the A/B value sets instead of reducing both in
// every lane: bit3=0 lanes finish A's sums, bit3=1 lanes finish B's.
// Softmax runs on the own set only (9 exp, was 18); one xor-8 shfl swaps the
// softmaxed sets back. 45 shfl/thread/j (was 72), MUFU halved.
// ---------------------------------------------------------------------------
#define GSN_STRIDE 10      // 9 n + 1 pad (words)  -> conflict-free LDS.64
#define GSH_STRIDE 264     // 256 h + 8 pad (words)

__global__ void __launch_bounds__(256, 2) attn_kernel(
    const int* __restrict__ nine_idx,
    const float* __restrict__ W_lin,
    const float* __restrict__ b_lin,
    float* __restrict__ out)
{
    __shared__ float Gsn[2][256 * GSN_STRIDE];
    __shared__ float Gsh[2][9 * GSH_STRIDE];
    __shared__ float sWl[512];
    __shared__ int   sidx[9];

    const int tid   = threadIdx.x;
    const int b     = blockIdx.x >> 1;
    const int ibase = (blockIdx.x & 1) * 32;
    const int iq    = tid >> 4;
    const int hq    = tid & 15;
    const int iA    = ibase + 2 * iq;
    const int iB    = iA + 1;
    const bool isB  = (tid & 8) != 0;   // bit3 of the 16-lane reduce group

    if (tid < 9) sidx[tid] = nine_idx[b * 9 + tid];
    sWl[tid] = W_lin[tid];
    sWl[256 + tid] = W_lin[256 + tid];
    __syncthreads();

    int idxr[9];
#pragma unroll
    for (int n = 0; n < 9; n++) idxr[n] = sidx[n];

    float hsA[16], hsB[16];
    {
        const float* HA = g_hs + ((size_t)iA * BB + b) * HH + hq;
        const float* HB = g_hs + ((size_t)iB * BB + b) * HH + hq;
#pragma unroll
        for (int e = 0; e < 16; e++) { hsA[e] = HA[16 * e]; hsB[e] = HB[16 * e]; }
    }

    u64 acc2[2][4][2];
#pragma unroll
    for (int i = 0; i < 2; i++)
#pragma unroll
        for (int c = 0; c < 4; c++) { acc2[i][c][0] = 0ULL; acc2[i][c][1] = 0ULL; }

    const float bl = b_lin[0];

    float gr[9];
#pragma unroll
    for (int n = 0; n < 9; n++) {
        int iv = idxr[n];
        gr[n] = (iv < BB) ? g_hs[(size_t)iv * HH + tid] : 0.f;
    }

    float* out_attn = out + (size_t)TT * BB;

    for (int j = 0; j < TT; j++) {
        float* gn = Gsn[j & 1];
        float* gh = Gsh[j & 1];
#pragma unroll
        for (int n = 0; n < 9; n++) gn[tid * GSN_STRIDE + n] = gr[n];
#pragma unroll
        for (int n = 0; n < 9; n++) gh[n * GSH_STRIDE + tid] = gr[n];
        __syncthreads();

        if (j < TT - 1) {
            const float* src = g_hs + (size_t)(j + 1) * BB * HH;
#pragma unroll
            for (int n = 0; n < 9; n++) {
                int iv = idxr[n];
                gr[n] = (iv < BB) ? src[(size_t)iv * HH + tid] : 0.f;
            }
        }

        u64 s2A[4], s2B[4];
        float s8A = 0.f, s8B = 0.f;
#pragma unroll
        for (int p = 0; p < 4; p++) { s2A[p] = 0ULL; s2B[p] = 0ULL; }

#pragma unroll
        for (int e = 0; e < 16; e++) {
            const float* base = gn + (hq + 16 * e) * GSN_STRIDE;
            u64 g01 = *reinterpret_cast<const u64*>(base);
            u64 g23 = *reinterpret_cast<const u64*>(base + 2);
            u64 g45 = *reinterpret_cast<const u64*>(base + 4);
            u64 g67 = *reinterpret_cast<const u64*>(base + 6);
            float g8v = base[8];
            float xA = hsA[e], xB = hsB[e];
            u64 xdA, xdB;
            PACK_F32X2(xdA, xA, xA);
            PACK_F32X2(xdB, xB, xB);
            FMA_F32X2(s2A[0], g01, xdA, s2A[0]);
            FMA_F32X2(s2A[1], g23, xdA, s2A[1]);
            FMA_F32X2(s2A[2], g45, xdA, s2A[2]);
            FMA_F32X2(s2A[3], g67, xdA, s2A[3]);
            FMA_F32X2(s2B[0], g01, xdB, s2B[0]);
            FMA_F32X2(s2B[1], g23, xdB, s2B[1]);
            FMA_F32X2(s2B[2], g45, xdB, s2B[2]);
            FMA_F32X2(s2B[3], g67, xdB, s2B[3]);
            s8A += xA * g8v;
            s8B += xB * g8v;
        }

        float pA[9], pB[9];
#pragma unroll
        for (int p = 0; p < 4; p++) {
            UNPACK_F32X2(pA[2*p], pA[2*p+1], s2A[p]);
            UNPACK_F32X2(pB[2*p], pB[2*p+1], s2B[p]);
        }
        pA[8] = s8A; pB[8] = s8B;

        // ---- split-reduce: own set finishes in own half (bit3) ----
        // pw[n] := full 16-lane sum of (isB ? pB : pA)
        float pw[9];
#pragma unroll
        for (int n = 0; n < 9; n++) {
            float send = isB ? pA[n] : pB[n];
            float keep = isB ? pB[n] : pA[n];
            float v = keep + __shfl_xor_sync(0xffffffffu, send, 8);
            v += __shfl_xor_sync(0xffffffffu, v, 1);
            v += __shfl_xor_sync(0xffffffffu, v, 2);
            v += __shfl_xor_sync(0xffffffffu, v, 4);
            pw[n] = v;
        }

        // softmax on own set only (9 exp, not 18)
        {
            float m = pw[0];
#pragma unroll
            for (int n = 1; n < 9; n++) m = fmaxf(m, pw[n]);
            float sum = 0.f;
#pragma unroll
            for (int n = 0; n < 9; n++) { pw[n] = __expf(pw[n] - m); sum += pw[n]; }
            float r = 1.f / sum;
#pragma unroll
            for (int n = 0; n < 9; n++) pw[n] *= r;
        }

        // swap softmaxed sets back so every lane holds both pA and pB
#pragma unroll
        for (int n = 0; n < 9; n++) {
            float other = __shfl_xor_sync(0xffffffffu, pw[n], 8);
            pA[n] = isB ? other : pw[n];
            pB[n] = isB ? pw[n] : other;
        }

        if (hq < 9) {
            out_attn[(((size_t)(iA * TT + j)) * BB + b) * 9 + hq] = pA[hq];
            out_attn[(((size_t)(iB * TT + j)) * BB + b) * 9 + hq] = pB[hq];
        }

        if (j < iB) {
            const bool dA = (j < iA);
#pragma unroll
            for (int n = 0; n < 9; n++) {
                float vA = dA ? pA[n] : 0.f;
                u64 pdA, pdB;
                PACK_F32X2(pdA, vA, vA);
                PACK_F32X2(pdB, pB[n], pB[n]);
                const float* rowp = gh + n * GSH_STRIDE + 4 * hq;
#pragma unroll
                for (int c = 0; c < 4; c++) {
                    ulonglong2 gv = *reinterpret_cast<const ulonglong2*>(rowp + 64 * c);
                    FMA_F32X2(acc2[0][c][0], pdA, gv.x, acc2[0][c][0]);
                    FMA_F32X2(acc2[0][c][1], pdA, gv.y, acc2[0][c][1]);
                    FMA_F32X2(acc2[1][c][0], pdB, gv.x, acc2[1][c][0]);
                    FMA_F32X2(acc2[1][c][1], pdB, gv.y, acc2[1][c][1]);
                }
            }
        }
    }

#pragma unroll
    for (int i = 0; i < 2; i++) {
        const int gi = (i == 0) ? iA : iB;
        const float* hrow = g_hs + ((size_t)gi * BB + b) * HH;
        float t = 0.f;
#pragma unroll
        for (int c = 0; c < 4; c++) {
            const int h0 = 4 * hq + 64 * c;
            float4 hv = *reinterpret_cast<const float4*>(hrow + h0);
            float a0, a1, a2, a3;
            UNPACK_F32X2(a0, a1, acc2[i][c][0]);
            UNPACK_F32X2(a2, a3, acc2[i][c][1]);
            if (gi == 0) { a0 = hv.x; a1 = hv.y; a2 = hv.z; a3 = hv.w; }
            t += a0 * sWl[h0]   + hv.x * sWl[256 + h0];
            t += a1 * sWl[h0+1] + hv.y * sWl[256 + h0 + 1];
            t += a2 * sWl[h0+2] + hv.z * sWl[256 + h0 + 2];
            t += a3 * sWl[h0+3] + hv.w * sWl[256 + h0 + 3];
        }
        t += __shfl_xor_sync(0xffffffffu, t, 1);
        t += __shfl_xor_sync(0xffffffffu, t, 2);
        t += __shfl_xor_sync(0xffffffffu, t, 4);
        t += __shfl_xor_sync(0xffffffffu, t, 8);
        if (hq == 0)
            out[(size_t)gi * BB + b] = fmaxf(t + bl, 0.f);
    }
}

// ---------------------------------------------------------------------------
extern "C" void kernel_launch(void* const* d_in, const int* in_sizes, int n_in,
                              void* d_out, int out_size)
{
    const float* data  = (const float*)d_in[0];
    const int*   nidx  = (const int*)d_in[1];
    /* d_in[2] = haven_flag (always 0, branch unused) */
    const float* h0    = (const float*)d_in[3];
    const float* W_ih  = (const float*)d_in[4];
    const float* W_hh  = (const float*)d_in[5];
    const float* b_ih  = (const float*)d_in[6];
    const float* b_hh  = (const float*)d_in[7];
    const float* W_lin = (const float*)d_in[8];
    const float* b_lin = (const float*)d_in[9];
    float* out = (float*)d_out;

    (void)in_sizes; (void)n_in; (void)out_size;

    wt_kernel<<<256, 256>>>(W_hh);
    xw_kernel<<<1024, 256>>>(data, W_ih, b_ih, b_hh);

    const int rnn_smem = (2 * 8 * 260 + 8 * 2048) * (int)sizeof(float);
    cudaFuncSetAttribute(rnn_scan_kernel,
                         cudaFuncAttributeMaxDynamicSharedMemorySize, rnn_smem);
    rnn_scan_kernel<<<128, 512, rnn_smem>>>(h0);

    attn_kernel<<<2048, 256>>>(nidx, W_lin, b_lin, out);
}

// round 15
// speedup vs baseline: 3.7171x; 1.0256x over previous
#include <cuda_runtime.h>

#define TT 64
#define BB 1024
#define II 64
#define HH 256

__device__ float g_hs[(size_t)TT * BB * HH];
__device__ float g_WT[HH * HH];   // WT[k][h] = W_hh[h][k]

typedef unsigned long long u64;

#define FMA_F32X2(d, a, b, c) \
    asm("fma.rn.f32x2 %0, %1, %2, %3;" : "=l"(d) : "l"(a), "l"(b), "l"(c))
#define PACK_F32X2(out, lo, hi) \
    asm("mov.b64 %0, {%1, %2};" : "=l"(out) : "f"(lo), "f"(hi))
#define UNPACK_F32X2(lo, hi, in) \
    asm("mov.b64 {%0, %1}, %2;" : "=f"(lo), "=f"(hi) : "l"(in))

// ---------------------------------------------------------------------------
// Kernel 0: transpose W_hh (one-time, 256 KB)
// ---------------------------------------------------------------------------
__global__ void __launch_bounds__(256) wt_kernel(const float* __restrict__ W_hh)
{
    const int k = blockIdx.x;
    const int h = threadIdx.x;
    g_WT[k * HH + h] = W_hh[h * HH + k];
}

// ---------------------------------------------------------------------------
// Kernel 1: g_hs[t,b,h] = data[t,b,:] . W_ih[h,:] + b_ih[h] + b_hh[h]
// ---------------------------------------------------------------------------
__global__ void __launch_bounds__(256) xw_kernel(
    const float* __restrict__ data,
    const float* __restrict__ W_ih,
    const float* __restrict__ b_ih,
    const float* __restrict__ b_hh)
{
    __shared__ float sX[256];
    const int tid = threadIdx.x;
    const long r0 = (long)blockIdx.x * 64;

    float w[64];
    const float4* W4 = reinterpret_cast<const float4*>(W_ih) + tid * 16;
#pragma unroll
    for (int c = 0; c < 16; c++) {
        float4 v = W4[c];
        w[4*c+0] = v.x; w[4*c+1] = v.y; w[4*c+2] = v.z; w[4*c+3] = v.w;
    }
    const float bsum = b_ih[tid] + b_hh[tid];

    for (int rg = 0; rg < 16; rg++) {
        __syncthreads();
        sX[tid] = data[r0 * II + rg * 256 + tid];
        __syncthreads();
        float a0 = bsum, a1 = bsum, a2 = bsum, a3 = bsum;
        const float4* X4 = reinterpret_cast<const float4*>(sX);
#pragma unroll
        for (int c = 0; c < 16; c++) {
            float4 x;
            x = X4[c];      a0 += x.x*w[4*c] + x.y*w[4*c+1] + x.z*w[4*c+2] + x.w*w[4*c+3];
            x = X4[16+c];   a1 += x.x*w[4*c] + x.y*w[4*c+1] + x.z*w[4*c+2] + x.w*w[4*c+3];
            x = X4[32+c];   a2 += x.x*w[4*c] + x.y*w[4*c+1] + x.z*w[4*c+2] + x.w*w[4*c+3];
            x = X4[48+c];   a3 += x.x*w[4*c] + x.y*w[4*c+1] + x.z*w[4*c+2] + x.w*w[4*c+3];
        }
        long r = r0 + rg * 4;
        g_hs[(r+0)*HH + tid] = a0;
        g_hs[(r+1)*HH + tid] = a1;
        g_hs[(r+2)*HH + tid] = a2;
        g_hs[(r+3)*HH + tid] = a3;
    }
}

// ---------------------------------------------------------------------------
// Kernel 2: persistent RNN scan, k-split (validated).
// ---------------------------------------------------------------------------
__global__ void __launch_bounds__(512) rnn_scan_kernel(
    const float* __restrict__ h0_in)
{
    extern __shared__ float sm[];
    float* hp   = sm;                 // [2][8][260]
    float* part = sm + 2 * 8 * 260;   // [8][2048]

    const int tid = threadIdx.x;
    const int kq = tid >> 6;
    const int hw = tid & 63;
    const int b0 = blockIdx.x * 8;

    for (int m = tid; m < 2048; m += 512) {
        int bb = m >> 8, k = m & 255;
        hp[bb * 260 + k] = h0_in[(size_t)(b0 + bb) * HH + k];
    }
    __syncthreads();

    const int off = tid * 4;
    const int rb_b = off >> 8;
    const int rb_h = off & 255;

    for (int t = 0; t < TT; t++) {
        const int rb = t & 1;
        const float* hpc = hp + rb * 8 * 260;

        u64 acc[8][2];
#pragma unroll
        for (int bb = 0; bb < 8; bb++) { acc[bb][0] = 0ULL; acc[bb][1] = 0ULL; }

#pragma unroll 2
        for (int k4 = 0; k4 < 8; k4++) {
            const int k = kq * 32 + k4 * 4;
            const ulonglong2* wr =
                reinterpret_cast<const ulonglong2*>(g_WT + (size_t)k * HH) + hw;
            ulonglong2 w0 = wr[0];
            ulonglong2 w1 = wr[64];
            ulonglong2 w2 = wr[128];
            ulonglong2 w3 = wr[192];
#pragma unroll
            for (int bb = 0; bb < 8; bb++) {
                float4 hv = *reinterpret_cast<const float4*>(hpc + bb * 260 + k);
                u64 hd;
                PACK_F32X2(hd, hv.x, hv.x);
                FMA_F32X2(acc[bb][0], w0.x, hd, acc[bb][0]);
                FMA_F32X2(acc[bb][1], w0.y, hd, acc[bb][1]);
                PACK_F32X2(hd, hv.y, hv.y);
                FMA_F32X2(acc[bb][0], w1.x, hd, acc[bb][0]);
                FMA_F32X2(acc[bb][1], w1.y, hd, acc[bb][1]);
                PACK_F32X2(hd, hv.z, hv.z);
                FMA_F32X2(acc[bb][0], w2.x, hd, acc[bb][0]);
                FMA_F32X2(acc[bb][1], w2.y, hd, acc[bb][1]);
                PACK_F32X2(hd, hv.w, hv.w);
                FMA_F32X2(acc[bb][0], w3.x, hd, acc[bb][0]);
                FMA_F32X2(acc[bb][1], w3.y, hd, acc[bb][1]);
            }
        }

#pragma unroll
        for (int bb = 0; bb < 8; bb++) {
            float f0, f1, f2, f3;
            UNPACK_F32X2(f0, f1, acc[bb][0]);
            UNPACK_F32X2(f2, f3, acc[bb][1]);
            *reinterpret_cast<float4*>(part + kq * 2048 + bb * 256 + hw * 4) =
                make_float4(f0, f1, f2, f3);
        }
        __syncthreads();

        {
            float* hs_t = g_hs + (size_t)t * BB * HH;
            float4 r = *reinterpret_cast<const float4*>(
                hs_t + (size_t)(b0 + rb_b) * HH + rb_h);
#pragma unroll
            for (int q = 0; q < 8; q++) {
                float4 pv = *reinterpret_cast<const float4*>(part + q * 2048 + off);
                r.x += pv.x; r.y += pv.y; r.z += pv.z; r.w += pv.w;
            }
            r.x = fmaxf(r.x, 0.f); r.y = fmaxf(r.y, 0.f);
            r.z = fmaxf(r.z, 0.f); r.w = fmaxf(r.w, 0.f);
            *reinterpret_cast<float4*>(
                hs_t + (size_t)(b0 + rb_b) * HH + rb_h) = r;
            *reinterpret_cast<float4*>(
                hp + (rb ^ 1) * 8 * 260 + rb_b * 260 + rb_h) = r;
        }
        __syncthreads();
    }
}

// ---------------------------------------------------------------------------
// Kernel 3: attention. ONE block per b (512 thr, all 64 i) — G tile staged
// once per b. Gsn layout is the VALIDATED unswizzled R13 one (stride 10,
// no group shift — the R14 swizzle overflowed into the next row group and
// corrupted 8 cells/buffer). Threads <256 stage the gather tile.
// Split-reduce butterfly + single barrier per j retained.
// ---------------------------------------------------------------------------
#define GSN_STRIDE 10
#define GSN_SZ     2560      // 255*10 + 9, rounded up
#define GSH_STRIDE 264       // 256 h + 8 pad (words)

__global__ void __launch_bounds__(512, 1) attn_kernel(
    const int* __restrict__ nine_idx,
    const float* __restrict__ W_lin,
    const float* __restrict__ b_lin,
    float* __restrict__ out)
{
    __shared__ float Gsn[2][GSN_SZ];
    __shared__ float Gsh[2][9 * GSH_STRIDE];
    __shared__ float sWl[512];
    __shared__ int   sidx[9];

    const int tid   = threadIdx.x;
    const int b     = blockIdx.x;
    const int iq    = tid >> 4;          // 0..31
    const int hq    = tid & 15;          // 0..15
    const int iA    = 2 * iq;
    const int iB    = iA + 1;
    const bool isB  = (tid & 8) != 0;    // bit3 of the 16-lane reduce group
    const bool stager = (tid < 256);     // threads that stage the gather tile

    if (tid < 9) sidx[tid] = nine_idx[b * 9 + tid];
    sWl[tid] = W_lin[tid];
    __syncthreads();

    int idxr[9];
#pragma unroll
    for (int n = 0; n < 9; n++) idxr[n] = sidx[n];

    float hsA[16], hsB[16];
    {
        const float* HA = g_hs + ((size_t)iA * BB + b) * HH + hq;
        const float* HB = g_hs + ((size_t)iB * BB + b) * HH + hq;
#pragma unroll
        for (int e = 0; e < 16; e++) { hsA[e] = HA[16 * e]; hsB[e] = HB[16 * e]; }
    }

    u64 acc2[2][4][2];
#pragma unroll
    for (int i = 0; i < 2; i++)
#pragma unroll
        for (int c = 0; c < 4; c++) { acc2[i][c][0] = 0ULL; acc2[i][c][1] = 0ULL; }

    const float bl = b_lin[0];

    // stagers prefetch gather rows for j = 0 (row h = tid)
    float gr[9];
    if (stager) {
#pragma unroll
        for (int n = 0; n < 9; n++) {
            int iv = idxr[n];
            gr[n] = (iv < BB) ? g_hs[(size_t)iv * HH + tid] : 0.f;
        }
    }

    const int gn_st = tid * GSN_STRIDE;   // unswizzled (validated layout)

    float* out_attn = out + (size_t)TT * BB;

    for (int j = 0; j < TT; j++) {
        float* gn = Gsn[j & 1];
        float* gh = Gsh[j & 1];
        if (stager) {
#pragma unroll
            for (int n = 0; n < 9; n++) gn[gn_st + n] = gr[n];
#pragma unroll
            for (int n = 0; n < 9; n++) gh[n * GSH_STRIDE + tid] = gr[n];
        }
        __syncthreads();

        if (stager && j < TT - 1) {
            const float* src = g_hs + (size_t)(j + 1) * BB * HH;
#pragma unroll
            for (int n = 0; n < 9; n++) {
                int iv = idxr[n];
                gr[n] = (iv < BB) ? src[(size_t)iv * HH + tid] : 0.f;
            }
        }

        u64 s2A[4], s2B[4];
        float s8A = 0.f, s8B = 0.f;
#pragma unroll
        for (int p = 0; p < 4; p++) { s2A[p] = 0ULL; s2B[p] = 0ULL; }

#pragma unroll
        for (int e = 0; e < 16; e++) {
            const float* base = gn + (hq + 16 * e) * GSN_STRIDE;
            u64 g01 = *reinterpret_cast<const u64*>(base);
            u64 g23 = *reinterpret_cast<const u64*>(base + 2);
            u64 g45 = *reinterpret_cast<const u64*>(base + 4);
            u64 g67 = *reinterpret_cast<const u64*>(base + 6);
            float g8v = base[8];
            float xA = hsA[e], xB = hsB[e];
            u64 xdA, xdB;
            PACK_F32X2(xdA, xA, xA);
            PACK_F32X2(xdB, xB, xB);
            FMA_F32X2(s2A[0], g01, xdA, s2A[0]);
            FMA_F32X2(s2A[1], g23, xdA, s2A[1]);
            FMA_F32X2(s2A[2], g45, xdA, s2A[2]);
            FMA_F32X2(s2A[3], g67, xdA, s2A[3]);
            FMA_F32X2(s2B[0], g01, xdB, s2B[0]);
            FMA_F32X2(s2B[1], g23, xdB, s2B[1]);
            FMA_F32X2(s2B[2], g45, xdB, s2B[2]);
            FMA_F32X2(s2B[3], g67, xdB, s2B[3]);
            s8A += xA * g8v;
            s8B += xB * g8v;
        }

        float pA[9], pB[9];
#pragma unroll
        for (int p = 0; p < 4; p++) {
            UNPACK_F32X2(pA[2*p], pA[2*p+1], s2A[p]);
            UNPACK_F32X2(pB[2*p], pB[2*p+1], s2B[p]);
        }
        pA[8] = s8A; pB[8] = s8B;

        // split-reduce: own set finishes in own bit3-half
        float pw[9];
#pragma unroll
        for (int n = 0; n < 9; n++) {
            float send = isB ? pA[n] : pB[n];
            float keep = isB ? pB[n] : pA[n];
            float v = keep + __shfl_xor_sync(0xffffffffu, send, 8);
            v += __shfl_xor_sync(0xffffffffu, v, 1);
            v += __shfl_xor_sync(0xffffffffu, v, 2);
            v += __shfl_xor_sync(0xffffffffu, v, 4);
            pw[n] = v;
        }

        // softmax on own set only
        {
            float m = pw[0];
#pragma unroll
            for (int n = 1; n < 9; n++) m = fmaxf(m, pw[n]);
            float sum = 0.f;
#pragma unroll
            for (int n = 0; n < 9; n++) { pw[n] = __expf(pw[n] - m); sum += pw[n]; }
            float r = 1.f / sum;
#pragma unroll
            for (int n = 0; n < 9; n++) pw[n] *= r;
        }

        // swap softmaxed sets back
#pragma unroll
        for (int n = 0; n < 9; n++) {
            float other = __shfl_xor_sync(0xffffffffu, pw[n], 8);
            pA[n] = isB ? other : pw[n];
            pB[n] = isB ? pw[n] : other;
        }

        if (hq < 9) {
            out_attn[(((size_t)(iA * TT + j)) * BB + b) * 9 + hq] = pA[hq];
            out_attn[(((size_t)(iB * TT + j)) * BB + b) * 9 + hq] = pB[hq];
        }

        if (j < iB) {
            const bool dA = (j < iA);
#pragma unroll
            for (int n = 0; n < 9; n++) {
                float vA = dA ? pA[n] : 0.f;
                u64 pdA, pdB;
                PACK_F32X2(pdA, vA, vA);
                PACK_F32X2(pdB, pB[n], pB[n]);
                const float* rowp = gh + n * GSH_STRIDE + 4 * hq;
#pragma unroll
                for (int c = 0; c < 4; c++) {
                    ulonglong2 gv = *reinterpret_cast<const ulonglong2*>(rowp + 64 * c);
                    FMA_F32X2(acc2[0][c][0], pdA, gv.x, acc2[0][c][0]);
                    FMA_F32X2(acc2[0][c][1], pdA, gv.y, acc2[0][c][1]);
                    FMA_F32X2(acc2[1][c][0], pdB, gv.x, acc2[1][c][0]);
                    FMA_F32X2(acc2[1][c][1], pdB, gv.y, acc2[1][c][1]);
                }
            }
        }
    }

#pragma unroll
    for (int i = 0; i < 2; i++) {
        const int gi = (i == 0) ? iA : iB;
        const float* hrow = g_hs + ((size_t)gi * BB + b) * HH;
        float t = 0.f;
#pragma unroll
        for (int c = 0; c < 4; c++) {
            const int h0 = 4 * hq + 64 * c;
            float4 hv = *reinterpret_cast<const float4*>(hrow + h0);
            float a0, a1, a2, a3;
            UNPACK_F32X2(a0, a1, acc2[i][c][0]);
            UNPACK_F32X2(a2, a3, acc2[i][c][1]);
            if (gi == 0) { a0 = hv.x; a1 = hv.y; a2 = hv.z; a3 = hv.w; }
            t += a0 * sWl[h0]   + hv.x * sWl[256 + h0];
            t += a1 * sWl[h0+1] + hv.y * sWl[256 + h0 + 1];
            t += a2 * sWl[h0+2] + hv.z * sWl[256 + h0 + 2];
            t += a3 * sWl[h0+3] + hv.w * sWl[256 + h0 + 3];
        }
        t += __shfl_xor_sync(0xffffffffu, t, 1);
        t += __shfl_xor_sync(0xffffffffu, t, 2);
        t += __shfl_xor_sync(0xffffffffu, t, 4);
        t += __shfl_xor_sync(0xffffffffu, t, 8);
        if (hq == 0)
            out[(size_t)gi * BB + b] = fmaxf(t + bl, 0.f);
    }
}

// ---------------------------------------------------------------------------
extern "C" void kernel_launch(void* const* d_in, const int* in_sizes, int n_in,
                              void* d_out, int out_size)
{
    const float* data  = (const float*)d_in[0];
    const int*   nidx  = (const int*)d_in[1];
    /* d_in[2] = haven_flag (always 0, branch unused) */
    const float* h0    = (const float*)d_in[3];
    const float* W_ih  = (const float*)d_in[4];
    const float* W_hh  = (const float*)d_in[5];
    const float* b_ih  = (const float*)d_in[6];
    const float* b_hh  = (const float*)d_in[7];
    const float* W_lin = (const float*)d_in[8];
    const float* b_lin = (const float*)d_in[9];
    float* out = (float*)d_out;

    (void)in_sizes; (void)n_in; (void)out_size;

    wt_kernel<<<256, 256>>>(W_hh);
    xw_kernel<<<1024, 256>>>(data, W_ih, b_ih, b_hh);

    const int rnn_smem = (2 * 8 * 260 + 8 * 2048) * (int)sizeof(float);
    cudaFuncSetAttribute(rnn_scan_kernel,
                         cudaFuncAttributeMaxDynamicSharedMemorySize, rnn_smem);
    rnn_scan_kernel<<<128, 512, rnn_smem>>>(h0);

    attn_kernel<<<1024, 512>>>(nidx, W_lin, b_lin, out);
}